// round 16
// baseline (speedup 1.0000x reference)
#include <cuda_runtime.h>
#include <cuda_fp16.h>
#include <cstdint>

#define C_CH     64
#define NIN      2144
#define NINP     2176        // padded to 34*64
#define OUT_CH   256
#define HW       4096
#define KC       64
#define NCHUNK   34
#define PX_CTA   128
#define NTH      640         // 16 consumer warps + 4 producer warps
#define NSTAGE   3

// ---------------- prep storage (device globals) ----------------
// W per chunk: [chunk][n=256][128B row], SW128 pre-swizzled fp16, zero-padded.
#define WCHUNK_BYTES 32768
__device__ __align__(16) unsigned char g_w[NCHUNK * WCHUNK_BYTES];
__device__ __align__(16) uchar2 g_pairs[NINP];   // {i, j}; j==64 => constant-1 channel

// ---------------- smem layout (dynamic) ----------------
// XS : x tile [65 ch][128 px] fp32 (row 64 = 1.0f) = 33280 B   @ 0
// PS : pair table 2176 uchar2                      =  4352 B   @ 33280
// MB : 6 mbarriers (full[3], empty[3])             =    64 B   @ 37632
// Y  : 3 stages x [128 px][128 B] fp16 SW128       = 49152 B   @ 38912
// W  : 3 stages x [256 n ][128 B] fp16 SW128       = 98304 B   @ 88064
// Epilogue reuses [0, 34816) as fp32 [64][136] buffer.
#define SM_XS    0
#define SM_PS    33280
#define SM_MB    37632
#define SM_Y     38912
#define Y_STAGE  16384
#define SM_W     88064
#define W_STAGE  32768
#define SM_TOT   186368

// ---------------- asm helpers ----------------
__device__ __forceinline__ void ldsm4(uint32_t (&r)[4], uint32_t addr) {
    asm volatile("ldmatrix.sync.aligned.m8n8.x4.shared.b16 {%0,%1,%2,%3}, [%4];"
                 : "=r"(r[0]), "=r"(r[1]), "=r"(r[2]), "=r"(r[3]) : "r"(addr));
}
__device__ __forceinline__ void mma16816(float (&c)[4], const uint32_t (&a)[4],
                                         uint32_t b0, uint32_t b1) {
    asm volatile(
        "mma.sync.aligned.m16n8k16.row.col.f32.f16.f16.f32 "
        "{%0,%1,%2,%3}, {%4,%5,%6,%7}, {%8,%9}, {%0,%1,%2,%3};"
        : "+f"(c[0]), "+f"(c[1]), "+f"(c[2]), "+f"(c[3])
        : "r"(a[0]), "r"(a[1]), "r"(a[2]), "r"(a[3]), "r"(b0), "r"(b1));
}
__device__ __forceinline__ void cp_async16(uint32_t saddr, const void* gptr) {
    asm volatile("cp.async.cg.shared.global [%0], [%1], 16;"
                 :: "r"(saddr), "l"(gptr) : "memory");
}
__device__ __forceinline__ void mbar_init(uint32_t mbar, uint32_t cnt) {
    asm volatile("mbarrier.init.shared.b64 [%0], %1;" :: "r"(mbar), "r"(cnt) : "memory");
}
__device__ __forceinline__ void mbar_arrive(uint32_t mbar) {
    asm volatile("mbarrier.arrive.shared.b64 _, [%0];" :: "r"(mbar) : "memory");
}
__device__ __forceinline__ void mbar_wait(uint32_t mbar, uint32_t parity) {
    uint32_t done;
    asm volatile("{\n\t.reg .pred p;\n\t"
        "mbarrier.try_wait.parity.acquire.cta.shared::cta.b64 p, [%1], %2;\n\t"
        "selp.b32 %0, 1, 0, p;\n\t}"
        : "=r"(done) : "r"(mbar), "r"(parity) : "memory");
    while (!done) {
        asm volatile("{\n\t.reg .pred p;\n\t"
            "mbarrier.try_wait.parity.acquire.cta.shared::cta.b64 p, [%1], %2, 0x989680;\n\t"
            "selp.b32 %0, 1, 0, p;\n\t}"
            : "=r"(done) : "r"(mbar), "r"(parity) : "memory");
    }
}

// ---------------- prep kernel: flat (chunk,row,kp) items, coalesced ----------------
__global__ void w_prep_kernel(const float* __restrict__ w) {
    const int gid = blockIdx.x * 256 + threadIdx.x;

    if (blockIdx.x == 0) {           // pair table
        int t = threadIdx.x;
        if (t < C_CH) {
            int i = t;
            g_pairs[i] = make_uchar2((unsigned char)i, 64);
            int base = C_CH + C_CH * i - (i * (i - 1)) / 2;
            for (int j = i; j < C_CH; j++)
                g_pairs[base + (j - i)] = make_uchar2((unsigned char)i, (unsigned char)j);
        }
        if (t >= 64 && t < 96)       // padding pairs (W is zero there)
            g_pairs[NIN + (t - 64)] = make_uchar2(0, 64);
    }

    const int kp = gid & 31;                 // 0..31 (2 k each)
    const int n  = (gid >> 5) & 255;         // output row
    const int c  = gid >> 13;                // chunk
    const int k  = c * KC + 2 * kp;

    const float* wr = w + (size_t)n * NIN;
    float f0 = (k     < NIN) ? wr[k]     : 0.0f;
    float f1 = (k + 1 < NIN) ? wr[k + 1] : 0.0f;
    __half2 h2 = __floats2half2_rn(f0, f1);
    int kl   = 2 * kp;
    int phys = (((kl >> 3) ^ (n & 7)) << 4) + (kl & 7) * 2;   // SW128
    *(uint32_t*)(g_w + (size_t)c * WCHUNK_BYTES + n * 128 + phys) = *(uint32_t*)&h2;
}

// ---------------- main kernel: warp-specialized producer/consumer ----------------
__global__ __launch_bounds__(NTH, 1)
void quad_hmma_kernel(const float* __restrict__ x, float* __restrict__ out) {
    extern __shared__ __align__(1024) unsigned char smem[];
    const int tid  = threadIdx.x;
    const int wid  = tid >> 5;
    const int lane = tid & 31;
    const uint32_t sb = (uint32_t)__cvta_generic_to_shared(smem);

    float*  xs = (float*)(smem + SM_XS);
    uchar2* ps = (uchar2*)(smem + SM_PS);

    // ---- global pixel tile ----
    const int p0  = blockIdx.x * PX_CTA;
    const int b   = p0 >> 12;
    const int hw0 = p0 & 4095;
    const float* xb = x + (((size_t)b * C_CH) << 12) + hw0;

    // ---- mbarriers: full[s] @ SM_MB+s*8 (count 128), empty[s] @ +24 (count 16) ----
    if (tid == 0) {
        #pragma unroll
        for (int s = 0; s < NSTAGE; s++) {
            mbar_init(sb + SM_MB + s * 8, 128);       // producer threads
            mbar_init(sb + SM_MB + 24 + s * 8, 16);   // consumer warps
        }
    }

    // ---- load x tile: 64 ch x 128 px (2048 float4) + ones row + pairs ----
    #pragma unroll
    for (int t = 0; t < 4; t++) {
        int e = tid + t * NTH;
        if (e < 2048) {
            int ch = e >> 5;
            int po = (e & 31) << 2;
            *(float4*)(xs + ch * 128 + po) = *(const float4*)(xb + ((size_t)ch << 12) + po);
        }
    }
    if (tid < 32) *(float4*)(xs + 64 * 128 + tid * 4) = make_float4(1.f, 1.f, 1.f, 1.f);
    if (tid < NINP / 8) ((uint4*)ps)[tid] = ((const uint4*)g_pairs)[tid];
    __syncthreads();

    float acc[2][8][4];
    #pragma unroll
    for (int mt = 0; mt < 2; mt++)
        #pragma unroll
        for (int j = 0; j < 8; j++)
            #pragma unroll
            for (int q = 0; q < 4; q++) acc[mt][j][q] = 0.0f;

    if (wid >= 16) {
        // ================= PRODUCER (4 warps, 128 threads) =================
        const int pt = tid - 512;            // pixel 0..127
        const float* xcol = xs + pt;
        unsigned char* yrow_base = smem + SM_Y + pt * 128;
        const uint32_t wdst0 = sb + SM_W;
        int pstage = 0, pphase = 1;          // first empty-wait passes

        for (int c = 0; c < NCHUNK; c++) {
            mbar_wait(sb + SM_MB + 24 + pstage * 8, pphase);

            // W chunk -> stage (16 uint4/thread, linear, pre-swizzled)
            const unsigned char* src = g_w + (size_t)c * WCHUNK_BYTES;
            uint32_t wdst = wdst0 + pstage * W_STAGE;
            #pragma unroll
            for (int i = 0; i < 16; i++) {
                uint32_t off = (uint32_t)(pt + i * 128) * 16;
                cp_async16(wdst + off, src + off);
            }
            asm volatile("cp.async.commit_group;" ::: "memory");

            // build Y row pt, all 64 k (8 groups of 8 k)
            unsigned char* yrow = yrow_base + pstage * Y_STAGE;
            const uint4* pp = (const uint4*)((const unsigned char*)ps + c * 128);
            #pragma unroll
            for (int g = 0; g < 8; g++) {
                uint4 P = pp[g];             // 8 pairs
                uint32_t wsrc[4] = {P.x, P.y, P.z, P.w};
                uint32_t hv[4];
                #pragma unroll
                for (int q = 0; q < 4; q++) {
                    uint32_t w_ = wsrc[q];
                    float a0 = xcol[(w_ & 255u) << 7];
                    float b0 = xcol[((w_ >> 8) & 255u) << 7];
                    float a1 = xcol[((w_ >> 16) & 255u) << 7];
                    float b1 = xcol[(w_ >> 24) << 7];
                    __half2 h = __float22half2_rn(make_float2(a0 * b0, a1 * b1));
                    hv[q] = *(uint32_t*)&h;
                }
                *(uint4*)(yrow + (((uint32_t)(g ^ (pt & 7))) << 4)) =
                    make_uint4(hv[0], hv[1], hv[2], hv[3]);
            }

            asm volatile("cp.async.wait_group 0;" ::: "memory");
            mbar_arrive(sb + SM_MB + pstage * 8);      // full: W landed + Y stored
            if (++pstage == NSTAGE) { pstage = 0; pphase ^= 1; }
        }
    } else {
        // ================= CONSUMER (16 warps, 4m x 4n) =================
        const int wm = wid >> 2;             // 0..3, 32 px each (phase id)
        const int wn = wid & 3;              // 0..3, 64 ch each
        const uint32_t l7    = lane & 7;
        const uint32_t aRow  = (uint32_t)(wm * 32 + (lane & 15)) * 128;
        const uint32_t aHalf = (uint32_t)(lane >> 4);
        const uint32_t bRow  = (uint32_t)(wn * 64 + ((lane >> 4) << 3) + (lane & 7)) * 128;
        const uint32_t bHalf = (uint32_t)((lane >> 3) & 1);

        uint32_t aF[2][4], bF[4][4];
        int cstage = 0, cphase = 0;

#define LDA(sl) { _Pragma("unroll") for (int mt = 0; mt < 2; mt++) \
    ldsm4(aF[mt], ycur + aRow + mt * 2048 + (((((sl) * 2) + aHalf) ^ l7) << 4)); }
#define LDB(sl) { _Pragma("unroll") for (int nt = 0; nt < 4; nt++) \
    ldsm4(bF[nt], wcur + bRow + nt * 2048 + (((((sl) * 2) + bHalf) ^ l7) << 4)); }
#define DOMMA() { _Pragma("unroll") for (int mt = 0; mt < 2; mt++) \
    _Pragma("unroll") for (int j = 0; j < 8; j++) \
        mma16816(acc[mt][j], aF[mt], bF[j >> 1][(j & 1) * 2], bF[j >> 1][(j & 1) * 2 + 1]); }

        for (int c = 0; c < NCHUNK; c++) {
            mbar_wait(sb + SM_MB + cstage * 8, cphase);
            const uint32_t ycur = sb + SM_Y + cstage * Y_STAGE;
            const uint32_t wcur = sb + SM_W + cstage * W_STAGE;

            #pragma unroll
            for (int ks = 0; ks < 4; ks++) {
                const int sl = (ks + wm) & 3;
                LDA(sl); LDB(sl);
                DOMMA();
            }

            __syncwarp();
            if (lane == 0) mbar_arrive(sb + SM_MB + 24 + cstage * 8);
            if (++cstage == NSTAGE) { cstage = 0; cphase ^= 1; }
        }
#undef LDA
#undef LDB
#undef DOMMA
    }

    // ---- epilogue: transpose via smem, coalesced stores (all 640 threads) ----
    float* buf = (float*)smem;                       // [64][136] fp32
    float* ob  = out + ((size_t)b * OUT_CH) * HW + hw0;
    const int wm_e = wid >> 2;
    const int wn_e = wid & 3;
    #pragma unroll 1
    for (int slab = 0; slab < 4; slab++) {
        __syncthreads();
        if (wid < 16 && wn_e == slab) {
            #pragma unroll
            for (int mt = 0; mt < 2; mt++)
                #pragma unroll
                for (int j = 0; j < 8; j++) {
                    int px = wm_e * 32 + mt * 16 + (lane >> 2);
                    int ch = j * 8 + (lane & 3) * 2;
                    buf[ch * 136 + px]           = acc[mt][j][0];
                    buf[(ch + 1) * 136 + px]     = acc[mt][j][1];
                    buf[ch * 136 + px + 8]       = acc[mt][j][2];
                    buf[(ch + 1) * 136 + px + 8] = acc[mt][j][3];
                }
        }
        __syncthreads();
        #pragma unroll
        for (int t = 0; t < 4; t++) {
            int e = tid + t * NTH;                   // 0..2559, use 0..2047
            if (e < 2048) {
                int chl = e >> 5;
                int po  = (e & 31) << 2;
                float4 v = *(float4*)(buf + chl * 136 + po);
                *(float4*)(ob + (size_t)(slab * 64 + chl) * HW + po) = v;
            }
        }
    }
}

// ---------------- launch ----------------
extern "C" void kernel_launch(void* const* d_in, const int* in_sizes, int n_in,
                              void* d_out, int out_size) {
    const float* x = (const float*)d_in[0];    // [B, 64, 64, 64] fp32
    const float* w = (const float*)d_in[1];    // [256, 2144] fp32
    float* out = (float*)d_out;                // [B, 256, 64, 64] fp32

    int pixels = in_sizes[0] / C_CH;           // B * 4096

    cudaFuncSetAttribute(quad_hmma_kernel,
                         cudaFuncAttributeMaxDynamicSharedMemorySize, SM_TOT);

    w_prep_kernel<<<1088, 256>>>(w);
    quad_hmma_kernel<<<pixels / PX_CTA, NTH, SM_TOT>>>(x, out);
}